// round 5
// baseline (speedup 1.0000x reference)
#include <cuda_runtime.h>
#include <cstdint>

#define BLOCK    256
#define ROWS     1024
#define STAGES   4
#define NBLOCKS  296                 // 148 SMs * 2 blocks
#define SLOT_F   (ROWS * 6)          // floats per slot: 5120 in + 1024 tgt
#define IN_BYTES (ROWS * 5 * 4)      // 20480
#define TG_BYTES (ROWS * 4)          // 4096
#define TX_BYTES (IN_BYTES + TG_BYTES)
#define SMEM_BYTES (STAGES * SLOT_F * 4)   // 98304

__device__ float g_partials[NBLOCKS];
__device__ unsigned int g_count = 0;

__device__ __forceinline__ uint32_t smem_u32(const void* p) {
    return (uint32_t)__cvta_generic_to_shared(p);
}
__device__ __forceinline__ void mbar_init(uint32_t mbar, uint32_t count) {
    asm volatile("mbarrier.init.shared.b64 [%0], %1;" :: "r"(mbar), "r"(count) : "memory");
}
__device__ __forceinline__ void mbar_expect_tx(uint32_t mbar, uint32_t bytes) {
    asm volatile("mbarrier.arrive.expect_tx.shared.b64 _, [%0], %1;"
                 :: "r"(mbar), "r"(bytes) : "memory");
}
__device__ __forceinline__ void mbar_wait(uint32_t mbar, uint32_t parity) {
    uint32_t done;
    asm volatile("{\n\t.reg .pred p;\n\t"
                 "mbarrier.try_wait.parity.acquire.cta.shared::cta.b64 p, [%1], %2;\n\t"
                 "selp.b32 %0, 1, 0, p;\n\t}"
                 : "=r"(done) : "r"(mbar), "r"(parity) : "memory");
    if (!done) {
        asm volatile("{\n\t.reg .pred P1;\n\t"
                     "W%=:\n\t"
                     "mbarrier.try_wait.parity.acquire.cta.shared::cta.b64 P1, [%0], %1, 0x989680;\n\t"
                     "@P1 bra.uni D%=;\n\t"
                     "bra.uni W%=;\n\t"
                     "D%=:\n\t}"
                     :: "r"(mbar), "r"(parity) : "memory");
    }
}
__device__ __forceinline__ void bulk_cp(uint32_t dst_smem, const void* src, uint32_t bytes,
                                        uint32_t mbar) {
    asm volatile("cp.async.bulk.shared::cluster.global.mbarrier::complete_tx::bytes "
                 "[%0], [%1], %2, [%3];"
                 :: "r"(dst_smem), "l"(src), "r"(bytes), "r"(mbar) : "memory");
}

__global__ void __launch_bounds__(BLOCK)
loss_kernel(const float* __restrict__ in,
            const float* __restrict__ tgt,
            long long nrows,
            float* __restrict__ out)
{
    extern __shared__ __align__(16) float smem[];   // STAGES * SLOT_F floats
    __shared__ __align__(8) uint64_t mbar_store[STAGES];

    const int tid = threadIdx.x;
    const long long fulltiles = nrows / ROWS;
    const long long step = gridDim.x;
    const long long t0 = blockIdx.x;
    float acc = 0.0f;

    if (tid == 0) {
        #pragma unroll
        for (int s = 0; s < STAGES; s++)
            mbar_init(smem_u32(&mbar_store[s]), 1);
    }
    __syncthreads();

    // Tail rows handled by block 0 directly (256 rows for N=20M).
    if (blockIdx.x == 0) {
        for (long long r = fulltiles * ROWS + tid; r < nrows; r += BLOCK) {
            const float x0 = in[r * 5 + 0];
            const float x2 = in[r * 5 + 2];
            const float x4 = in[r * 5 + 4];
            const float t  = tgt[r];
            const float d  = (fabsf(x4 - x2) < 0.1f) ? (x0 - x4) : (x0 - t);
            acc += fabsf(d);
        }
    }

    auto stage = [&](int slot, long long tile) {
        if (tid == 0 && tile < fulltiles) {
            const uint32_t mb = smem_u32(&mbar_store[slot]);
            mbar_expect_tx(mb, TX_BYTES);
            const uint32_t sb = smem_u32(&smem[slot * SLOT_F]);
            bulk_cp(sb, in + tile * (long long)ROWS * 5, IN_BYTES, mb);
            bulk_cp(sb + IN_BYTES, tgt + tile * ROWS, TG_BYTES, mb);
        }
    };

    #pragma unroll
    for (int k = 0; k < STAGES; k++)
        stage(k, t0 + (long long)k * step);

    int cnt = 0;
    for (long long t = t0; t < fulltiles; t += step, cnt++) {
        const int slot = cnt % STAGES;
        const uint32_t parity = (uint32_t)((cnt / STAGES) & 1);
        mbar_wait(smem_u32(&mbar_store[slot]), parity);

        const float* s = &smem[slot * SLOT_F];
        const float* st = s + ROWS * 5;
        #pragma unroll
        for (int j = 0; j < ROWS / BLOCK; j++) {
            const int r = tid + j * BLOCK;
            const float x0 = s[r * 5 + 0];
            const float x2 = s[r * 5 + 2];
            const float x4 = s[r * 5 + 4];
            const float tv = st[r];
            const float d  = (fabsf(x4 - x2) < 0.1f) ? (x0 - x4) : (x0 - tv);
            acc += fabsf(d);
        }

        __syncthreads();                       // all done reading slot
        stage(slot, t + (long long)STAGES * step);
    }
    __syncthreads();                           // pipeline drained (all issued tiles consumed)

    // Warp reduce then block reduce (reuse smem as scratch).
    #pragma unroll
    for (int off = 16; off > 0; off >>= 1)
        acc += __shfl_down_sync(0xFFFFFFFFu, acc, off);
    if ((tid & 31) == 0) smem[tid >> 5] = acc;
    __syncthreads();

    __shared__ int s_last;
    if (tid == 0) {
        float v = 0.0f;
        #pragma unroll
        for (int w = 0; w < BLOCK / 32; w++) v += smem[w];
        g_partials[blockIdx.x] = v;
        __threadfence();
        const unsigned int old = atomicAdd(&g_count, 1u);
        s_last = (old == gridDim.x - 1);
    }
    __syncthreads();

    // Last block: deterministic double-precision final reduce.
    if (s_last) {
        double* sd = reinterpret_cast<double*>(&smem[0]);   // 16B-aligned
        double a = 0.0;
        for (int i = tid; i < NBLOCKS; i += BLOCK)
            a += (double)g_partials[i];
        #pragma unroll
        for (int off = 16; off > 0; off >>= 1)
            a += __shfl_down_sync(0xFFFFFFFFu, a, off);
        __syncthreads();
        if ((tid & 31) == 0) sd[tid >> 5] = a;
        __syncthreads();
        if (tid == 0) {
            double sum = 0.0;
            #pragma unroll
            for (int w = 0; w < BLOCK / 32; w++) sum += sd[w];
            out[0] = (float)(sum / (double)nrows);
            g_count = 0;    // reset for next graph replay (determinism)
        }
    }
}

extern "C" void kernel_launch(void* const* d_in, const int* in_sizes, int n_in,
                              void* d_out, int out_size)
{
    static bool configured = false;
    if (!configured) {
        cudaFuncSetAttribute(loss_kernel,
                             cudaFuncAttributeMaxDynamicSharedMemorySize,
                             SMEM_BYTES);
        configured = true;
    }

    const float* inputs  = (const float*)d_in[0];   // [N, 5] fp32
    const float* targets = (const float*)d_in[1];   // [N, 1] fp32
    float* out = (float*)d_out;

    const long long nrows = (long long)in_sizes[0] / 5;

    loss_kernel<<<NBLOCKS, BLOCK, SMEM_BYTES>>>(inputs, targets, nrows, out);
}